// round 16
// baseline (speedup 1.0000x reference)
#include <cuda_runtime.h>
#include <cuda_fp16.h>
#include <math.h>
#include <stdint.h>

#define NMAX 100000
#define EMAX 1600000
#define DF   128
#define NG   128
#define NP   64
#define NC   10
#define NBMAX 128

// ---------------- scratch (static device globals; no allocs allowed) --------
__device__ __align__(16) int    g_deg_out[NMAX];
__device__ __align__(16) int    g_deg_in[NMAX];
__device__ __align__(16) float  g_norm_out[NMAX];
__device__ __align__(16) float  g_norm_in[NMAX];
__device__ __align__(16) int    g_off[NMAX + 1];
__device__ __align__(16) int    g_cursor[NMAX];
__device__ __align__(16) int    g_csr_src[EMAX];
__device__ __align__(16) __half g_bufH[(size_t)NMAX * DF];
__device__ __align__(16) __half g_bufHA[(size_t)NMAX * DF];
__device__ __align__(16) __half g_W1t[DF * DF];
__device__ __align__(16) __half g_W2t[DF * DF];
__device__ __align__(16) float  g_hg[NG * DF];
__device__ __align__(16) float  g_cnt[NG];
__device__ __align__(16) int    g_agg[NBMAX];
__device__ __align__(16) int    g_flagA[NBMAX];

// ---------------- init ------------------------------------------------------
__global__ void k_zero(int n) {
    int i = blockIdx.x * blockDim.x + threadIdx.x;
    int stride = gridDim.x * blockDim.x;
    for (int j = i; j < n; j += stride) { g_deg_out[j] = 0; g_deg_in[j] = 0; }
    for (int j = i; j < NBMAX; j += stride) g_flagA[j] = 0;
}

// ---------------- degree histogram: 4 edges per thread (MLP) ----------------
__global__ void k_deg(const int* __restrict__ src,
                      const int* __restrict__ dst, int e) {
    int i = blockIdx.x * blockDim.x + threadIdx.x;
    int i4 = i * 4;
    if (i4 + 3 < e) {
        int4 s = *(const int4*)&src[i4];
        int4 d = *(const int4*)&dst[i4];
        atomicAdd(&g_deg_out[s.x], 1); atomicAdd(&g_deg_out[s.y], 1);
        atomicAdd(&g_deg_out[s.z], 1); atomicAdd(&g_deg_out[s.w], 1);
        atomicAdd(&g_deg_in[d.x], 1);  atomicAdd(&g_deg_in[d.y], 1);
        atomicAdd(&g_deg_in[d.z], 1);  atomicAdd(&g_deg_in[d.w], 1);
    } else if (i4 < e) {
        for (int j = i4; j < e; j++) {
            atomicAdd(&g_deg_out[src[j]], 1);
            atomicAdd(&g_deg_in[dst[j]], 1);
        }
    }
}

// ---------------- single-pass scan: parallel lookback -----------------------
__global__ void k_scan(int n, int e) {
    __shared__ int sh[1024];
    __shared__ int s_part[4];
    __shared__ int s_pref;
    int t = threadIdx.x, b = blockIdx.x;

    int idx = b * 1024 + t;
    int v = (idx < n) ? g_deg_in[idx] : 0;
    sh[t] = v;
    __syncthreads();
    for (int s = 1; s < 1024; s <<= 1) {
        int x = (t >= s) ? sh[t - s] : 0;
        __syncthreads();
        sh[t] += x;
        __syncthreads();
    }
    if (t == 0) {
        g_agg[b] = sh[1023];
        __threadfence();
        atomicExch(&g_flagA[b], 1);
    }
    if (t < 128) {
        int pv = 0;
        if (t < b) {
            while (atomicAdd(&g_flagA[t], 0) == 0) { }
            pv = g_agg[t];
        }
        for (int o = 16; o; o >>= 1) pv += __shfl_down_sync(0xffffffffu, pv, o);
        if ((t & 31) == 0) s_part[t >> 5] = pv;
    }
    __syncthreads();
    if (t == 0) s_pref = s_part[0] + s_part[1] + s_part[2] + s_part[3];
    __syncthreads();

    int excl = sh[t] - v;
    if (idx < n) {
        int o = s_pref + excl;
        g_off[idx] = o;
        g_cursor[idx] = o;
    }
    if (b == 0 && t == 0) g_off[n] = e;
}

// ---------------- CSR fill: 4 edges per thread (MLP) ------------------------
__global__ void k_fill(const int* __restrict__ src,
                       const int* __restrict__ dst, int e) {
    int i = blockIdx.x * blockDim.x + threadIdx.x;
    int i4 = i * 4;
    if (i4 + 3 < e) {
        int4 s = *(const int4*)&src[i4];
        int4 d = *(const int4*)&dst[i4];
        int p0 = atomicAdd(&g_cursor[d.x], 1);
        int p1 = atomicAdd(&g_cursor[d.y], 1);
        int p2 = atomicAdd(&g_cursor[d.z], 1);
        int p3 = atomicAdd(&g_cursor[d.w], 1);
        g_csr_src[p0] = s.x; g_csr_src[p1] = s.y;
        g_csr_src[p2] = s.z; g_csr_src[p3] = s.w;
    } else if (i4 < e) {
        for (int j = i4; j < e; j++) {
            int p = atomicAdd(&g_cursor[dst[j]], 1);
            g_csr_src[p] = src[j];
        }
    }
}

// ---------------- prep: norms + h*out_norm -> fp16, W -> fp16^T, zero hg ----
__global__ void k_prep(const float* __restrict__ h,
                       const float* __restrict__ W1,
                       const float* __restrict__ W2, int n) {
    int j = blockIdx.x * blockDim.x + threadIdx.x;
    int total = n * 32;
    if (j < total) {
        int node = j >> 5;
        int lane = j & 31;
        float s = rsqrtf(fmaxf((float)g_deg_out[node], 1.0f));
        if (lane == 0) {
            g_norm_out[node] = s;
            g_norm_in[node]  = rsqrtf(fmaxf((float)g_deg_in[node], 1.0f));
        }
        float4 v = ((const float4*)h)[j];
        __half2 h0 = __floats2half2_rn(v.x * s, v.y * s);
        __half2 h1 = __floats2half2_rn(v.z * s, v.w * s);
        uint2 o;
        o.x = *(uint32_t*)&h0;
        o.y = *(uint32_t*)&h1;
        ((uint2*)g_bufH)[j] = o;
    } else if (j < total + DF * DF) {
        int i = j - total;
        int nn = i >> 7, k = i & 127;
        g_W1t[nn * DF + k] = __float2half_rn(W1[k * DF + nn]);
    } else if (j < total + 2 * DF * DF) {
        int i = j - total - DF * DF;
        int nn = i >> 7, k = i & 127;
        g_W2t[nn * DF + k] = __float2half_rn(W2[k * DF + nn]);
    } else if (j < total + 2 * DF * DF + NG * DF) {
        g_hg[j - total - 2 * DF * DF] = 0.0f;
    } else if (j < total + 2 * DF * DF + NG * DF + NG) {
        g_cnt[j - total - 2 * DF * DF - NG * DF] = 0.0f;
    }
}

// ---------------- aggregation: one warp per dst node, 16 lanes/edge ---------
#define ACC4(vv) \
    a0 = __hadd2(a0, *(__half2*)&(vv).x); a1 = __hadd2(a1, *(__half2*)&(vv).y); \
    a2 = __hadd2(a2, *(__half2*)&(vv).z); a3 = __hadd2(a3, *(__half2*)&(vv).w);

__global__ void k_agg_h(const __half* __restrict__ xh, __half* __restrict__ out, int n) {
    int w = (blockIdx.x * blockDim.x + threadIdx.x) >> 5;
    int lane = threadIdx.x & 31;
    if (w >= n) return;
    int beg = g_off[w], end = g_off[w + 1];
    float wi = g_norm_in[w];      // hoisted: L2 latency overlaps the gather loop
    int hs = lane >> 4;
    int fl = lane & 15;
    const uint4* __restrict__ x4 = (const uint4*)xh;

    __half2 a0 = __float2half2_rn(0.f), a1 = a0, a2 = a0, a3 = a0;

    int e = beg;
    for (; e + 15 < end; e += 16) {
        int s0 = g_csr_src[e + hs];
        int s1 = g_csr_src[e + 2 + hs];
        int s2 = g_csr_src[e + 4 + hs];
        int s3 = g_csr_src[e + 6 + hs];
        int s4 = g_csr_src[e + 8 + hs];
        int s5 = g_csr_src[e + 10 + hs];
        int s6 = g_csr_src[e + 12 + hs];
        int s7 = g_csr_src[e + 14 + hs];
        uint4 v0 = x4[(size_t)s0 * 16 + fl];
        uint4 v1 = x4[(size_t)s1 * 16 + fl];
        uint4 v2 = x4[(size_t)s2 * 16 + fl];
        uint4 v3 = x4[(size_t)s3 * 16 + fl];
        uint4 v4 = x4[(size_t)s4 * 16 + fl];
        uint4 v5 = x4[(size_t)s5 * 16 + fl];
        uint4 v6 = x4[(size_t)s6 * 16 + fl];
        uint4 v7 = x4[(size_t)s7 * 16 + fl];
        ACC4(v0) ACC4(v1) ACC4(v2) ACC4(v3)
        ACC4(v4) ACC4(v5) ACC4(v6) ACC4(v7)
    }
    if (e + 7 < end) {
        int s0 = g_csr_src[e + hs];
        int s1 = g_csr_src[e + 2 + hs];
        int s2 = g_csr_src[e + 4 + hs];
        int s3 = g_csr_src[e + 6 + hs];
        uint4 v0 = x4[(size_t)s0 * 16 + fl];
        uint4 v1 = x4[(size_t)s1 * 16 + fl];
        uint4 v2 = x4[(size_t)s2 * 16 + fl];
        uint4 v3 = x4[(size_t)s3 * 16 + fl];
        ACC4(v0) ACC4(v1) ACC4(v2) ACC4(v3)
        e += 8;
    }
    for (; e + 1 < end; e += 2) {
        int s0 = g_csr_src[e + hs];
        uint4 v0 = x4[(size_t)s0 * 16 + fl];
        ACC4(v0)
    }
    if (e < end && hs == 0) {
        int s0 = g_csr_src[e];
        uint4 v0 = x4[(size_t)s0 * 16 + fl];
        ACC4(v0)
    }

    uint32_t b;
    b = __shfl_xor_sync(0xffffffffu, *(uint32_t*)&a0, 16); a0 = __hadd2(a0, *(__half2*)&b);
    b = __shfl_xor_sync(0xffffffffu, *(uint32_t*)&a1, 16); a1 = __hadd2(a1, *(__half2*)&b);
    b = __shfl_xor_sync(0xffffffffu, *(uint32_t*)&a2, 16); a2 = __hadd2(a2, *(__half2*)&b);
    b = __shfl_xor_sync(0xffffffffu, *(uint32_t*)&a3, 16); a3 = __hadd2(a3, *(__half2*)&b);

    if (lane < 16) {
        float2 f0 = __half22float2(a0), f1 = __half22float2(a1);
        float2 f2 = __half22float2(a2), f3 = __half22float2(a3);
        __half2 o0 = __floats2half2_rn(f0.x * wi, f0.y * wi);
        __half2 o1 = __floats2half2_rn(f1.x * wi, f1.y * wi);
        __half2 o2 = __floats2half2_rn(f2.x * wi, f2.y * wi);
        __half2 o3 = __floats2half2_rn(f3.x * wi, f3.y * wi);
        uint4 o;
        o.x = *(uint32_t*)&o0; o.y = *(uint32_t*)&o1;
        o.z = *(uint32_t*)&o2; o.w = *(uint32_t*)&o3;
        ((uint4*)out)[(size_t)w * 16 + fl] = o;
    }
}

// ---------------- fp16 tensor-core GEMM with cp.async 2-stage pipeline ------
__device__ __forceinline__ void mma_f16(float* c, const uint32_t* a, const uint32_t* b) {
    asm volatile(
        "mma.sync.aligned.m16n8k16.row.col.f32.f16.f16.f32 "
        "{%0,%1,%2,%3}, {%4,%5,%6,%7}, {%8,%9}, {%0,%1,%2,%3};"
        : "+f"(c[0]), "+f"(c[1]), "+f"(c[2]), "+f"(c[3])
        : "r"(a[0]), "r"(a[1]), "r"(a[2]), "r"(a[3]), "r"(b[0]), "r"(b[1]));
}

__device__ __forceinline__ void cp16(uint32_t smem_addr, const void* gptr, bool valid) {
    int sz = valid ? 16 : 0;
    asm volatile("cp.async.cg.shared.global [%0], [%1], 16, %2;"
                 :: "r"(smem_addr), "l"(gptr), "r"(sz));
}

#define KCH 64
#define TILE_H (128 * 72)          // halves per tile
#define GSM_BYTES (4 * TILE_H * 2) // 73728

template <int RELU>
__global__ __launch_bounds__(256) void k_gemm_h(const __half* __restrict__ A,
                                                const __half* __restrict__ Wt,
                                                const float* __restrict__ bias,
                                                const float* __restrict__ rowscale,
                                                __half* __restrict__ CoutH,
                                                int n) {
    extern __shared__ __half smp[];
    __half* tiles[4] = { smp, smp + TILE_H, smp + 2 * TILE_H, smp + 3 * TILE_H };

    int tid = threadIdx.x;
    int lane = tid & 31;
    int warp = tid >> 5;
    int warpM = warp & 3;
    int warpN = warp >> 2;
    int g = lane >> 2, t = lane & 3;
    int rowBase = blockIdx.x * 128;

    uint32_t smemBase = (uint32_t)__cvta_generic_to_shared(smp);

#pragma unroll
    for (int s = 0; s < 2; s++) {
        int k0 = s * KCH;
        uint32_t aBase = smemBase + (2 * s) * TILE_H * 2;
        uint32_t bBase = smemBase + (2 * s + 1) * TILE_H * 2;
#pragma unroll
        for (int i = tid; i < 1024; i += 256) {
            int r = i >> 3, c = (i & 7) * 8;
            int gr = rowBase + r;
            cp16(aBase + (r * 72 + c) * 2, &A[(size_t)gr * 128 + k0 + c], gr < n);
        }
#pragma unroll
        for (int i = tid; i < 1024; i += 256) {
            int r = i >> 3, c = (i & 7) * 8;
            cp16(bBase + (r * 72 + c) * 2, &Wt[r * 128 + k0 + c], true);
        }
        asm volatile("cp.async.commit_group;" ::: "memory");
    }

    float acc[2][8][4];
#pragma unroll
    for (int mt = 0; mt < 2; mt++)
#pragma unroll
        for (int nt = 0; nt < 8; nt++)
#pragma unroll
            for (int i = 0; i < 4; i++) acc[mt][nt][i] = 0.0f;

#pragma unroll
    for (int s = 0; s < 2; s++) {
        if (s == 0) asm volatile("cp.async.wait_group 1;" ::: "memory");
        else        asm volatile("cp.async.wait_group 0;" ::: "memory");
        __syncthreads();
        const __half* sA = tiles[2 * s];
        const __half* sB = tiles[2 * s + 1];

#pragma unroll
        for (int kk = 0; kk < KCH; kk += 16) {
            uint32_t Af[2][4];
#pragma unroll
            for (int mt = 0; mt < 2; mt++) {
                int rb = warpM * 32 + mt * 16;
                Af[mt][0] = *(const uint32_t*)&sA[(rb + g) * 72 + kk + 2 * t];
                Af[mt][1] = *(const uint32_t*)&sA[(rb + g + 8) * 72 + kk + 2 * t];
                Af[mt][2] = *(const uint32_t*)&sA[(rb + g) * 72 + kk + 8 + 2 * t];
                Af[mt][3] = *(const uint32_t*)&sA[(rb + g + 8) * 72 + kk + 8 + 2 * t];
            }
            uint32_t Bf[8][2];
#pragma unroll
            for (int nt = 0; nt < 8; nt++) {
                int nb = warpN * 64 + nt * 8;
                Bf[nt][0] = *(const uint32_t*)&sB[(nb + g) * 72 + kk + 2 * t];
                Bf[nt][1] = *(const uint32_t*)&sB[(nb + g) * 72 + kk + 8 + 2 * t];
            }
#pragma unroll
            for (int mt = 0; mt < 2; mt++)
#pragma unroll
                for (int nt = 0; nt < 8; nt++)
                    mma_f16(acc[mt][nt], Af[mt], Bf[nt]);
        }
    }

#pragma unroll
    for (int mt = 0; mt < 2; mt++) {
        int r0 = rowBase + warpM * 32 + mt * 16 + g;
        int r1 = r0 + 8;
        float rs0 = 1.0f, rs1 = 1.0f;
        if (rowscale) {
            if (r0 < n) rs0 = rowscale[r0];
            if (r1 < n) rs1 = rowscale[r1];
        }
#pragma unroll
        for (int nt = 0; nt < 8; nt++) {
            int col = warpN * 64 + nt * 8 + 2 * t;
            float b0 = bias[col], b1 = bias[col + 1];
            float v0 = acc[mt][nt][0] + b0;
            float v1 = acc[mt][nt][1] + b1;
            float v2 = acc[mt][nt][2] + b0;
            float v3 = acc[mt][nt][3] + b1;
            if (RELU) {
                v0 = fmaxf(v0, 0.f); v1 = fmaxf(v1, 0.f);
                v2 = fmaxf(v2, 0.f); v3 = fmaxf(v3, 0.f);
            }
            v0 *= rs0; v1 *= rs0; v2 *= rs1; v3 *= rs1;
            __half2 p0 = __floats2half2_rn(v0, v1);
            __half2 p1 = __floats2half2_rn(v2, v3);
            if (r0 < n) *(__half2*)&CoutH[(size_t)r0 * 128 + col] = p0;
            if (r1 < n) *(__half2*)&CoutH[(size_t)r1 * 128 + col] = p1;
        }
    }
}

// ---------------- per-graph mean pooling: half2 lanes, 4 chunks/block -------
#define NPB 128
__global__ void k_pool(const __half* __restrict__ x,
                       const int* __restrict__ gids, int n) {
    int tid = threadIdx.x;
    int chunk = tid >> 6;          // 0..3
    int f = tid & 63;              // half2 feature index: features 2f, 2f+1
    int start = (blockIdx.x * 4 + chunk) * NPB;
    int end = min(start + NPB, n);
    if (start >= n) return;
    const __half2* __restrict__ x2 = (const __half2*)x;   // 64 half2 per row

    float2 sum = make_float2(0.f, 0.f);
    int cur = gids[start];
    int cnt = 0;
    for (int nd = start; nd < end; nd++) {
        int gid = gids[nd];
        if (gid != cur) {
            atomicAdd(&g_hg[cur * DF + 2 * f], sum.x);
            atomicAdd(&g_hg[cur * DF + 2 * f + 1], sum.y);
            if (f == 0) atomicAdd(&g_cnt[cur], (float)cnt);
            sum.x = 0.f; sum.y = 0.f; cnt = 0; cur = gid;
        }
        float2 v = __half22float2(x2[(size_t)nd * 64 + f]);
        sum.x += v.x; sum.y += v.y;
        cnt++;
    }
    atomicAdd(&g_hg[cur * DF + 2 * f], sum.x);
    atomicAdd(&g_hg[cur * DF + 2 * f + 1], sum.y);
    if (f == 0) atomicAdd(&g_cnt[cur], (float)cnt);
}

// ---------------- final classifier: [G, 128+64] @ Wc + bc -------------------
__global__ void k_final(const float* __restrict__ perm,
                        const float* __restrict__ Wc,
                        const float* __restrict__ bc,
                        float* __restrict__ out) {
    int g = blockIdx.x;
    int c = threadIdx.x;
    if (c >= NC) return;
    float inv = 1.0f / fmaxf(g_cnt[g], 1.0f);
    float acc = bc[c];
#pragma unroll 4
    for (int j = 0; j < DF; j++)
        acc += g_hg[g * DF + j] * inv * Wc[j * NC + c];
#pragma unroll 4
    for (int j = 0; j < NP; j++)
        acc += perm[g * NP + j] * Wc[(DF + j) * NC + c];
    out[g * NC + c] = acc;
}

// ---------------- launch ----------------------------------------------------
extern "C" void kernel_launch(void* const* d_in, const int* in_sizes, int n_in,
                              void* d_out, int out_size) {
    const float* h    = (const float*)d_in[0];
    const float* perm = (const float*)d_in[1];
    const float* W1   = (const float*)d_in[2];
    const float* b1   = (const float*)d_in[3];
    const float* W2   = (const float*)d_in[4];
    const float* b2   = (const float*)d_in[5];
    const float* Wc   = (const float*)d_in[6];
    const float* bc   = (const float*)d_in[7];
    const int* src  = (const int*)d_in[8];
    const int* dst  = (const int*)d_in[9];
    const int* gids = (const int*)d_in[10];

    int n = in_sizes[0] / DF;   // 100000
    int e = in_sizes[8];        // 1600000
    float* out = (float*)d_out;

    float *normOut;
    __half *bufH, *bufHA, *w1t, *w2t;
    cudaGetSymbolAddress((void**)&bufH, g_bufH);
    cudaGetSymbolAddress((void**)&bufHA, g_bufHA);
    cudaGetSymbolAddress((void**)&w1t, g_W1t);
    cudaGetSymbolAddress((void**)&w2t, g_W2t);
    cudaGetSymbolAddress((void**)&normOut, g_norm_out);

    int nb = (n + 1023) / 1024;                 // 98 <= NBMAX
    int gemmBlocks = (n + 127) / 128;
    int prepThreads = n * 32 + 2 * DF * DF + NG * DF + NG;
    int e4 = (e + 3) / 4;
    int poolBlocks = (n + 4 * NPB - 1) / (4 * NPB);

    cudaFuncSetAttribute(k_gemm_h<1>, cudaFuncAttributeMaxDynamicSharedMemorySize, GSM_BYTES);
    cudaFuncSetAttribute(k_gemm_h<0>, cudaFuncAttributeMaxDynamicSharedMemorySize, GSM_BYTES);

    k_zero<<<256, 256>>>(n);
    k_deg<<<(e4 + 255) / 256, 256>>>(src, dst, e);
    k_scan<<<nb, 1024>>>(n, e);
    k_fill<<<(e4 + 255) / 256, 256>>>(src, dst, e);
    k_prep<<<(prepThreads + 255) / 256, 256>>>(h, W1, W2, n);

    // layer 1: agg(bufH) -> bufHA ; gemm(bufHA, W1t)+relu, *out_norm -> bufH (fp16)
    k_agg_h<<<(n * 32 + 255) / 256, 256>>>(bufH, bufHA, n);
    k_gemm_h<1><<<gemmBlocks, 256, GSM_BYTES>>>(bufHA, w1t, b1, normOut, bufH, n);

    // layer 2: agg(bufH) -> bufHA ; gemm(bufHA, W2t) -> bufH (fp16)
    k_agg_h<<<(n * 32 + 255) / 256, 256>>>(bufH, bufHA, n);
    k_gemm_h<0><<<gemmBlocks, 256, GSM_BYTES>>>(bufHA, w2t, b2, (const float*)nullptr, bufH, n);

    // pooling + classifier
    k_pool<<<poolBlocks, 256>>>(bufH, gids, n);
    k_final<<<NG, 32>>>(perm, Wc, bc, out);
}

// round 17
// speedup vs baseline: 1.1167x; 1.1167x over previous
#include <cuda_runtime.h>
#include <cuda_fp16.h>
#include <math.h>
#include <stdint.h>

#define NMAX 100000
#define EMAX 1600000
#define DF   128
#define NG   128
#define NP   64
#define NC   10
#define NBMAX 128

// ---------------- scratch (static device globals; no allocs allowed) --------
__device__ __align__(16) int    g_deg_out[NMAX];
__device__ __align__(16) int    g_deg_in[NMAX];
__device__ __align__(16) float  g_norm_out[NMAX];
__device__ __align__(16) float  g_norm_in[NMAX];
__device__ __align__(16) int    g_off[NMAX + 1];
__device__ __align__(16) int    g_cursor[NMAX];
__device__ __align__(16) int    g_csr_src[EMAX];
__device__ __align__(16) __half g_bufH[(size_t)NMAX * DF];
__device__ __align__(16) __half g_bufHA[(size_t)NMAX * DF];
__device__ __align__(16) __half g_W1t[DF * DF];
__device__ __align__(16) __half g_W2t[DF * DF];
__device__ __align__(16) float  g_hg[NG * DF];
__device__ __align__(16) float  g_cnt[NG];
__device__ __align__(16) int    g_agg[NBMAX];
__device__ __align__(16) int    g_flagA[NBMAX];

// ---------------- init ------------------------------------------------------
__global__ void k_zero(int n) {
    int i = blockIdx.x * blockDim.x + threadIdx.x;
    int stride = gridDim.x * blockDim.x;
    for (int j = i; j < n; j += stride) { g_deg_out[j] = 0; g_deg_in[j] = 0; }
    for (int j = i; j < NG * DF; j += stride) g_hg[j] = 0.0f;
    for (int j = i; j < NG; j += stride) g_cnt[j] = 0.0f;
    for (int j = i; j < NBMAX; j += stride) g_flagA[j] = 0;
}

// ---------------- degree histogram: 4 edges per thread (MLP) ----------------
__global__ void k_deg(const int* __restrict__ src,
                      const int* __restrict__ dst, int e) {
    int i = blockIdx.x * blockDim.x + threadIdx.x;
    int i4 = i * 4;
    if (i4 + 3 < e) {
        int4 s = *(const int4*)&src[i4];
        int4 d = *(const int4*)&dst[i4];
        atomicAdd(&g_deg_out[s.x], 1); atomicAdd(&g_deg_out[s.y], 1);
        atomicAdd(&g_deg_out[s.z], 1); atomicAdd(&g_deg_out[s.w], 1);
        atomicAdd(&g_deg_in[d.x], 1);  atomicAdd(&g_deg_in[d.y], 1);
        atomicAdd(&g_deg_in[d.z], 1);  atomicAdd(&g_deg_in[d.w], 1);
    } else if (i4 < e) {
        for (int j = i4; j < e; j++) {
            atomicAdd(&g_deg_out[src[j]], 1);
            atomicAdd(&g_deg_in[dst[j]], 1);
        }
    }
}

// ---------------- single-pass scan: parallel lookback -----------------------
__global__ void k_scan(int n, int e) {
    __shared__ int sh[1024];
    __shared__ int s_part[4];
    __shared__ int s_pref;
    int t = threadIdx.x, b = blockIdx.x;

    int idx = b * 1024 + t;
    int v = (idx < n) ? g_deg_in[idx] : 0;
    sh[t] = v;
    __syncthreads();
    for (int s = 1; s < 1024; s <<= 1) {
        int x = (t >= s) ? sh[t - s] : 0;
        __syncthreads();
        sh[t] += x;
        __syncthreads();
    }
    if (t == 0) {
        g_agg[b] = sh[1023];
        __threadfence();
        atomicExch(&g_flagA[b], 1);
    }
    if (t < 128) {
        int pv = 0;
        if (t < b) {
            while (atomicAdd(&g_flagA[t], 0) == 0) { }
            pv = g_agg[t];
        }
        for (int o = 16; o; o >>= 1) pv += __shfl_down_sync(0xffffffffu, pv, o);
        if ((t & 31) == 0) s_part[t >> 5] = pv;
    }
    __syncthreads();
    if (t == 0) s_pref = s_part[0] + s_part[1] + s_part[2] + s_part[3];
    __syncthreads();

    int excl = sh[t] - v;
    if (idx < n) {
        int o = s_pref + excl;
        g_off[idx] = o;
        g_cursor[idx] = o;
    }
    if (b == 0 && t == 0) g_off[n] = e;
}

// ---------------- CSR fill: 4 edges per thread (MLP) ------------------------
__global__ void k_fill(const int* __restrict__ src,
                       const int* __restrict__ dst, int e) {
    int i = blockIdx.x * blockDim.x + threadIdx.x;
    int i4 = i * 4;
    if (i4 + 3 < e) {
        int4 s = *(const int4*)&src[i4];
        int4 d = *(const int4*)&dst[i4];
        int p0 = atomicAdd(&g_cursor[d.x], 1);
        int p1 = atomicAdd(&g_cursor[d.y], 1);
        int p2 = atomicAdd(&g_cursor[d.z], 1);
        int p3 = atomicAdd(&g_cursor[d.w], 1);
        g_csr_src[p0] = s.x; g_csr_src[p1] = s.y;
        g_csr_src[p2] = s.z; g_csr_src[p3] = s.w;
    } else if (i4 < e) {
        for (int j = i4; j < e; j++) {
            int p = atomicAdd(&g_cursor[dst[j]], 1);
            g_csr_src[p] = src[j];
        }
    }
}

// ---------------- prep: norms + h*out_norm -> fp16, W1/W2 -> fp16^T ---------
__global__ void k_prep(const float* __restrict__ h,
                       const float* __restrict__ W1,
                       const float* __restrict__ W2, int n) {
    int j = blockIdx.x * blockDim.x + threadIdx.x;
    int total = n * 32;
    if (j < total) {
        int node = j >> 5;
        int lane = j & 31;
        float s = rsqrtf(fmaxf((float)g_deg_out[node], 1.0f));
        if (lane == 0) {
            g_norm_out[node] = s;
            g_norm_in[node]  = rsqrtf(fmaxf((float)g_deg_in[node], 1.0f));
        }
        float4 v = ((const float4*)h)[j];
        __half2 h0 = __floats2half2_rn(v.x * s, v.y * s);
        __half2 h1 = __floats2half2_rn(v.z * s, v.w * s);
        uint2 o;
        o.x = *(uint32_t*)&h0;
        o.y = *(uint32_t*)&h1;
        ((uint2*)g_bufH)[j] = o;
    } else if (j < total + DF * DF) {
        int i = j - total;
        int nn = i >> 7, k = i & 127;
        g_W1t[nn * DF + k] = __float2half_rn(W1[k * DF + nn]);
    } else if (j < total + 2 * DF * DF) {
        int i = j - total - DF * DF;
        int nn = i >> 7, k = i & 127;
        g_W2t[nn * DF + k] = __float2half_rn(W2[k * DF + nn]);
    }
}

// ---------------- aggregation: one warp per dst node, 16 lanes/edge ---------
#define ACC4(vv) \
    a0 = __hadd2(a0, *(__half2*)&(vv).x); a1 = __hadd2(a1, *(__half2*)&(vv).y); \
    a2 = __hadd2(a2, *(__half2*)&(vv).z); a3 = __hadd2(a3, *(__half2*)&(vv).w);

__global__ void k_agg_h(const __half* __restrict__ xh, __half* __restrict__ out, int n) {
    int w = (blockIdx.x * blockDim.x + threadIdx.x) >> 5;
    int lane = threadIdx.x & 31;
    if (w >= n) return;
    int beg = g_off[w], end = g_off[w + 1];
    float wi = g_norm_in[w];      // hoisted: L2 latency overlaps the gather loop
    int hs = lane >> 4;
    int fl = lane & 15;
    const uint4* __restrict__ x4 = (const uint4*)xh;

    __half2 a0 = __float2half2_rn(0.f), a1 = a0, a2 = a0, a3 = a0;

    int e = beg;
    for (; e + 15 < end; e += 16) {
        int s0 = g_csr_src[e + hs];
        int s1 = g_csr_src[e + 2 + hs];
        int s2 = g_csr_src[e + 4 + hs];
        int s3 = g_csr_src[e + 6 + hs];
        int s4 = g_csr_src[e + 8 + hs];
        int s5 = g_csr_src[e + 10 + hs];
        int s6 = g_csr_src[e + 12 + hs];
        int s7 = g_csr_src[e + 14 + hs];
        uint4 v0 = x4[(size_t)s0 * 16 + fl];
        uint4 v1 = x4[(size_t)s1 * 16 + fl];
        uint4 v2 = x4[(size_t)s2 * 16 + fl];
        uint4 v3 = x4[(size_t)s3 * 16 + fl];
        uint4 v4 = x4[(size_t)s4 * 16 + fl];
        uint4 v5 = x4[(size_t)s5 * 16 + fl];
        uint4 v6 = x4[(size_t)s6 * 16 + fl];
        uint4 v7 = x4[(size_t)s7 * 16 + fl];
        ACC4(v0) ACC4(v1) ACC4(v2) ACC4(v3)
        ACC4(v4) ACC4(v5) ACC4(v6) ACC4(v7)
    }
    if (e + 7 < end) {
        int s0 = g_csr_src[e + hs];
        int s1 = g_csr_src[e + 2 + hs];
        int s2 = g_csr_src[e + 4 + hs];
        int s3 = g_csr_src[e + 6 + hs];
        uint4 v0 = x4[(size_t)s0 * 16 + fl];
        uint4 v1 = x4[(size_t)s1 * 16 + fl];
        uint4 v2 = x4[(size_t)s2 * 16 + fl];
        uint4 v3 = x4[(size_t)s3 * 16 + fl];
        ACC4(v0) ACC4(v1) ACC4(v2) ACC4(v3)
        e += 8;
    }
    for (; e + 1 < end; e += 2) {
        int s0 = g_csr_src[e + hs];
        uint4 v0 = x4[(size_t)s0 * 16 + fl];
        ACC4(v0)
    }
    if (e < end && hs == 0) {
        int s0 = g_csr_src[e];
        uint4 v0 = x4[(size_t)s0 * 16 + fl];
        ACC4(v0)
    }

    uint32_t b;
    b = __shfl_xor_sync(0xffffffffu, *(uint32_t*)&a0, 16); a0 = __hadd2(a0, *(__half2*)&b);
    b = __shfl_xor_sync(0xffffffffu, *(uint32_t*)&a1, 16); a1 = __hadd2(a1, *(__half2*)&b);
    b = __shfl_xor_sync(0xffffffffu, *(uint32_t*)&a2, 16); a2 = __hadd2(a2, *(__half2*)&b);
    b = __shfl_xor_sync(0xffffffffu, *(uint32_t*)&a3, 16); a3 = __hadd2(a3, *(__half2*)&b);

    if (lane < 16) {
        float2 f0 = __half22float2(a0), f1 = __half22float2(a1);
        float2 f2 = __half22float2(a2), f3 = __half22float2(a3);
        __half2 o0 = __floats2half2_rn(f0.x * wi, f0.y * wi);
        __half2 o1 = __floats2half2_rn(f1.x * wi, f1.y * wi);
        __half2 o2 = __floats2half2_rn(f2.x * wi, f2.y * wi);
        __half2 o3 = __floats2half2_rn(f3.x * wi, f3.y * wi);
        uint4 o;
        o.x = *(uint32_t*)&o0; o.y = *(uint32_t*)&o1;
        o.z = *(uint32_t*)&o2; o.w = *(uint32_t*)&o3;
        ((uint4*)out)[(size_t)w * 16 + fl] = o;
    }
}

// ---------------- fp16 tensor-core GEMM with cp.async 2-stage pipeline ------
__device__ __forceinline__ void mma_f16(float* c, const uint32_t* a, const uint32_t* b) {
    asm volatile(
        "mma.sync.aligned.m16n8k16.row.col.f32.f16.f16.f32 "
        "{%0,%1,%2,%3}, {%4,%5,%6,%7}, {%8,%9}, {%0,%1,%2,%3};"
        : "+f"(c[0]), "+f"(c[1]), "+f"(c[2]), "+f"(c[3])
        : "r"(a[0]), "r"(a[1]), "r"(a[2]), "r"(a[3]), "r"(b[0]), "r"(b[1]));
}

__device__ __forceinline__ void cp16(uint32_t smem_addr, const void* gptr, bool valid) {
    int sz = valid ? 16 : 0;
    asm volatile("cp.async.cg.shared.global [%0], [%1], 16, %2;"
                 :: "r"(smem_addr), "l"(gptr), "r"(sz));
}

#define KCH 64
#define TILE_H (128 * 72)          // halves per tile
#define GSM_BYTES (4 * TILE_H * 2) // 73728

template <int RELU>
__global__ __launch_bounds__(256) void k_gemm_h(const __half* __restrict__ A,
                                                const __half* __restrict__ Wt,
                                                const float* __restrict__ bias,
                                                const float* __restrict__ rowscale,
                                                __half* __restrict__ CoutH,
                                                int n) {
    extern __shared__ __half smp[];
    __half* tiles[4] = { smp, smp + TILE_H, smp + 2 * TILE_H, smp + 3 * TILE_H };

    int tid = threadIdx.x;
    int lane = tid & 31;
    int warp = tid >> 5;
    int warpM = warp & 3;
    int warpN = warp >> 2;
    int g = lane >> 2, t = lane & 3;
    int rowBase = blockIdx.x * 128;

    uint32_t smemBase = (uint32_t)__cvta_generic_to_shared(smp);

#pragma unroll
    for (int s = 0; s < 2; s++) {
        int k0 = s * KCH;
        uint32_t aBase = smemBase + (2 * s) * TILE_H * 2;
        uint32_t bBase = smemBase + (2 * s + 1) * TILE_H * 2;
#pragma unroll
        for (int i = tid; i < 1024; i += 256) {
            int r = i >> 3, c = (i & 7) * 8;
            int gr = rowBase + r;
            cp16(aBase + (r * 72 + c) * 2, &A[(size_t)gr * 128 + k0 + c], gr < n);
        }
#pragma unroll
        for (int i = tid; i < 1024; i += 256) {
            int r = i >> 3, c = (i & 7) * 8;
            cp16(bBase + (r * 72 + c) * 2, &Wt[r * 128 + k0 + c], true);
        }
        asm volatile("cp.async.commit_group;" ::: "memory");
    }

    float acc[2][8][4];
#pragma unroll
    for (int mt = 0; mt < 2; mt++)
#pragma unroll
        for (int nt = 0; nt < 8; nt++)
#pragma unroll
            for (int i = 0; i < 4; i++) acc[mt][nt][i] = 0.0f;

#pragma unroll
    for (int s = 0; s < 2; s++) {
        if (s == 0) asm volatile("cp.async.wait_group 1;" ::: "memory");
        else        asm volatile("cp.async.wait_group 0;" ::: "memory");
        __syncthreads();
        const __half* sA = tiles[2 * s];
        const __half* sB = tiles[2 * s + 1];

#pragma unroll
        for (int kk = 0; kk < KCH; kk += 16) {
            uint32_t Af[2][4];
#pragma unroll
            for (int mt = 0; mt < 2; mt++) {
                int rb = warpM * 32 + mt * 16;
                Af[mt][0] = *(const uint32_t*)&sA[(rb + g) * 72 + kk + 2 * t];
                Af[mt][1] = *(const uint32_t*)&sA[(rb + g + 8) * 72 + kk + 2 * t];
                Af[mt][2] = *(const uint32_t*)&sA[(rb + g) * 72 + kk + 8 + 2 * t];
                Af[mt][3] = *(const uint32_t*)&sA[(rb + g + 8) * 72 + kk + 8 + 2 * t];
            }
            uint32_t Bf[8][2];
#pragma unroll
            for (int nt = 0; nt < 8; nt++) {
                int nb = warpN * 64 + nt * 8;
                Bf[nt][0] = *(const uint32_t*)&sB[(nb + g) * 72 + kk + 2 * t];
                Bf[nt][1] = *(const uint32_t*)&sB[(nb + g) * 72 + kk + 8 + 2 * t];
            }
#pragma unroll
            for (int mt = 0; mt < 2; mt++)
#pragma unroll
                for (int nt = 0; nt < 8; nt++)
                    mma_f16(acc[mt][nt], Af[mt], Bf[nt]);
        }
    }

#pragma unroll
    for (int mt = 0; mt < 2; mt++) {
        int r0 = rowBase + warpM * 32 + mt * 16 + g;
        int r1 = r0 + 8;
        float rs0 = 1.0f, rs1 = 1.0f;
        if (rowscale) {
            if (r0 < n) rs0 = rowscale[r0];
            if (r1 < n) rs1 = rowscale[r1];
        }
#pragma unroll
        for (int nt = 0; nt < 8; nt++) {
            int col = warpN * 64 + nt * 8 + 2 * t;
            float b0 = bias[col], b1 = bias[col + 1];
            float v0 = acc[mt][nt][0] + b0;
            float v1 = acc[mt][nt][1] + b1;
            float v2 = acc[mt][nt][2] + b0;
            float v3 = acc[mt][nt][3] + b1;
            if (RELU) {
                v0 = fmaxf(v0, 0.f); v1 = fmaxf(v1, 0.f);
                v2 = fmaxf(v2, 0.f); v3 = fmaxf(v3, 0.f);
            }
            v0 *= rs0; v1 *= rs0; v2 *= rs1; v3 *= rs1;
            __half2 p0 = __floats2half2_rn(v0, v1);
            __half2 p1 = __floats2half2_rn(v2, v3);
            if (r0 < n) *(__half2*)&CoutH[(size_t)r0 * 128 + col] = p0;
            if (r1 < n) *(__half2*)&CoutH[(size_t)r1 * 128 + col] = p1;
        }
    }
}

// ---------------- per-graph mean pooling (graph_ids sorted), fp16 input -----
#define NPB 64
__global__ void k_pool(const __half* __restrict__ x,
                       const int* __restrict__ gids, int n) {
    int f = threadIdx.x;
    int start = blockIdx.x * NPB;
    int end = min(start + NPB, n);
    if (start >= n) return;
    float sum = 0.0f;
    int cur = gids[start];
    int cnt = 0;
    for (int nd = start; nd < end; nd++) {
        int gid = gids[nd];
        if (gid != cur) {
            atomicAdd(&g_hg[cur * DF + f], sum);
            if (f == 0) atomicAdd(&g_cnt[cur], (float)cnt);
            sum = 0.0f; cnt = 0; cur = gid;
        }
        sum += __half2float(x[(size_t)nd * DF + f]);
        cnt++;
    }
    atomicAdd(&g_hg[cur * DF + f], sum);
    if (f == 0) atomicAdd(&g_cnt[cur], (float)cnt);
}

// ---------------- final classifier: [G, 128+64] @ Wc + bc -------------------
__global__ void k_final(const float* __restrict__ perm,
                        const float* __restrict__ Wc,
                        const float* __restrict__ bc,
                        float* __restrict__ out) {
    int g = blockIdx.x;
    int c = threadIdx.x;
    if (c >= NC) return;
    float inv = 1.0f / fmaxf(g_cnt[g], 1.0f);
    float acc = bc[c];
#pragma unroll 4
    for (int j = 0; j < DF; j++)
        acc += g_hg[g * DF + j] * inv * Wc[j * NC + c];
#pragma unroll 4
    for (int j = 0; j < NP; j++)
        acc += perm[g * NP + j] * Wc[(DF + j) * NC + c];
    out[g * NC + c] = acc;
}

// ---------------- launch ----------------------------------------------------
extern "C" void kernel_launch(void* const* d_in, const int* in_sizes, int n_in,
                              void* d_out, int out_size) {
    const float* h    = (const float*)d_in[0];
    const float* perm = (const float*)d_in[1];
    const float* W1   = (const float*)d_in[2];
    const float* b1   = (const float*)d_in[3];
    const float* W2   = (const float*)d_in[4];
    const float* b2   = (const float*)d_in[5];
    const float* Wc   = (const float*)d_in[6];
    const float* bc   = (const float*)d_in[7];
    const int* src  = (const int*)d_in[8];
    const int* dst  = (const int*)d_in[9];
    const int* gids = (const int*)d_in[10];

    int n = in_sizes[0] / DF;   // 100000
    int e = in_sizes[8];        // 1600000
    float* out = (float*)d_out;

    float *normOut;
    __half *bufH, *bufHA, *w1t, *w2t;
    cudaGetSymbolAddress((void**)&bufH, g_bufH);
    cudaGetSymbolAddress((void**)&bufHA, g_bufHA);
    cudaGetSymbolAddress((void**)&w1t, g_W1t);
    cudaGetSymbolAddress((void**)&w2t, g_W2t);
    cudaGetSymbolAddress((void**)&normOut, g_norm_out);

    int nb = (n + 1023) / 1024;                 // 98 <= NBMAX
    int gemmBlocks = (n + 127) / 128;
    int prepThreads = n * 32 + 2 * DF * DF;
    int e4 = (e + 3) / 4;

    cudaFuncSetAttribute(k_gemm_h<1>, cudaFuncAttributeMaxDynamicSharedMemorySize, GSM_BYTES);
    cudaFuncSetAttribute(k_gemm_h<0>, cudaFuncAttributeMaxDynamicSharedMemorySize, GSM_BYTES);

    k_zero<<<256, 256>>>(n);
    k_deg<<<(e4 + 255) / 256, 256>>>(src, dst, e);
    k_scan<<<nb, 1024>>>(n, e);
    k_fill<<<(e4 + 255) / 256, 256>>>(src, dst, e);
    k_prep<<<(prepThreads + 255) / 256, 256>>>(h, W1, W2, n);

    // layer 1: agg(bufH) -> bufHA ; gemm(bufHA, W1t)+relu, *out_norm -> bufH (fp16)
    k_agg_h<<<(n * 32 + 255) / 256, 256>>>(bufH, bufHA, n);
    k_gemm_h<1><<<gemmBlocks, 256, GSM_BYTES>>>(bufHA, w1t, b1, normOut, bufH, n);

    // layer 2: agg(bufH) -> bufHA ; gemm(bufHA, W2t) -> bufH (fp16)
    k_agg_h<<<(n * 32 + 255) / 256, 256>>>(bufH, bufHA, n);
    k_gemm_h<0><<<gemmBlocks, 256, GSM_BYTES>>>(bufHA, w2t, b2, (const float*)nullptr, bufH, n);

    // pooling + classifier
    k_pool<<<(n + NPB - 1) / NPB, 128>>>(bufH, gids, n);
    k_final<<<NG, 32>>>(perm, Wc, bc, out);
}